// round 3
// baseline (speedup 1.0000x reference)
#include <cuda_runtime.h>

#define NB   64
#define LL   4500
#define KCH  64
#define NOUT 64

// ---------------- scratch (static device globals; no allocation) ------------
__device__ float g_h1[NB * KCH * LL];            // conv1 output        (73.7 MB)
__device__ float g_h2[NB * KCH * LL];            // conv2 output        (73.7 MB)
__device__ float g_sq[NB * KCH];                 // sum_l h2^2
__device__ float g_h5[NB * NOUT * 8 * LL];       // psi_mA conv output  (589.8 MB)
__device__ float g_coef[NB * NOUT * 8];          // routing coefficients

// ---------------- K0: zero the atomic accumulator ---------------------------
__global__ void k0_zero_sq() {
    int i = blockIdx.x * blockDim.x + threadIdx.x;
    if (i < NB * KCH) g_sq[i] = 0.f;
}

// ---------------- K1: conv1 (1 -> 64 channels, k=7, SAME) -------------------
__global__ __launch_bounds__(256) void k1_conv1(const float* __restrict__ x,
                                                const float* __restrict__ w1) {
    const int T = 512;
    __shared__ float xs[T + 6];
    __shared__ float ws[KCH * 7];
    int n  = blockIdx.y;
    int t0 = blockIdx.x * T;
    for (int i = threadIdx.x; i < KCH * 7; i += 256) ws[i] = w1[i];
    for (int i = threadIdx.x; i < T + 6; i += 256) {
        int g = t0 - 3 + i;
        xs[i] = (g >= 0 && g < LL) ? x[n * LL + g] : 0.f;
    }
    __syncthreads();
    for (int idx = threadIdx.x; idx < KCH * T; idx += 256) {
        int c = idx >> 9;          // T = 512
        int t = idx & 511;
        int gt = t0 + t;
        if (gt < LL) {
            float a = 0.f;
            #pragma unroll
            for (int d = 0; d < 7; d++) a = fmaf(xs[t + d], ws[c * 7 + d], a);
            g_h1[(n * KCH + c) * LL + gt] = a;
        }
    }
}

// ---------------- K2: conv2 (64 -> 64, k=5, SAME) + sum of squares ----------
// Tiled GEMM-style: block = (n, 128-wide L tile); thread = 4k x 8l microtile.
#define SMEM2_FLOATS (64 * 132 + 64 * 320 + 64)
__global__ __launch_bounds__(256) void k2_conv2(const float* __restrict__ w2) {
    extern __shared__ float sm[];
    float* h1s = sm;                 // [64][132]  tile + halo 2
    float* w2s = sm + 64 * 132;      // rearranged [c][dk][k]
    float* sqs = w2s + 64 * 320;     // [64]
    int n  = blockIdx.y;
    int l0 = blockIdx.x * 128;

    for (int i = threadIdx.x; i < 64 * 320; i += 256) {
        int k = i / 320; int r = i - k * 320; int c = r / 5; int dk = r - c * 5;
        w2s[c * 320 + dk * 64 + k] = w2[i];
    }
    for (int i = threadIdx.x; i < 64 * 132; i += 256) {
        int c = i / 132; int p = i - c * 132;
        int g = l0 - 2 + p;
        h1s[i] = (g >= 0 && g < LL) ? g_h1[(n * 64 + c) * LL + g] : 0.f;
    }
    if (threadIdx.x < 64) sqs[threadIdx.x] = 0.f;
    __syncthreads();

    int kg = threadIdx.x >> 4, lg = threadIdx.x & 15;
    int k0 = kg * 4, ll0 = lg * 8;

    float acc[4][8];
    #pragma unroll
    for (int a = 0; a < 4; a++)
        #pragma unroll
        for (int b = 0; b < 8; b++) acc[a][b] = 0.f;

    for (int c = 0; c < 64; c++) {
        const float* hr = h1s + c * 132 + ll0;          // 16B aligned
        float4 h0 = *(const float4*)(hr);
        float4 h4 = *(const float4*)(hr + 4);
        float4 h8 = *(const float4*)(hr + 8);
        float hv[12] = {h0.x, h0.y, h0.z, h0.w, h4.x, h4.y, h4.z, h4.w,
                        h8.x, h8.y, h8.z, h8.w};
        const float* wr = w2s + c * 320 + k0;
        #pragma unroll
        for (int dk = 0; dk < 5; dk++) {
            float4 wv = *(const float4*)(wr + dk * 64);
            #pragma unroll
            for (int ll = 0; ll < 8; ll++) {
                float h = hv[ll + dk];
                acc[0][ll] = fmaf(wv.x, h, acc[0][ll]);
                acc[1][ll] = fmaf(wv.y, h, acc[1][ll]);
                acc[2][ll] = fmaf(wv.z, h, acc[2][ll]);
                acc[3][ll] = fmaf(wv.w, h, acc[3][ll]);
            }
        }
    }

    float sloc[4] = {0.f, 0.f, 0.f, 0.f};
    #pragma unroll
    for (int kk = 0; kk < 4; kk++) {
        int row = (n * 64 + k0 + kk) * LL;
        #pragma unroll
        for (int v = 0; v < 2; v++) {
            int gl = l0 + ll0 + v * 4;
            if (gl < LL) {     // LL % 4 == 0 -> float4 never straddles the edge
                float4 st = {acc[kk][v * 4 + 0], acc[kk][v * 4 + 1],
                             acc[kk][v * 4 + 2], acc[kk][v * 4 + 3]};
                *(float4*)&g_h2[row + gl] = st;
                sloc[kk] += st.x * st.x + st.y * st.y + st.z * st.z + st.w * st.w;
            }
        }
    }
    #pragma unroll
    for (int kk = 0; kk < 4; kk++) atomicAdd(&sqs[k0 + kk], sloc[kk]);
    __syncthreads();
    if (threadIdx.x < 64) atomicAdd(&g_sq[n * 64 + threadIdx.x], sqs[threadIdx.x]);
}

// ---------------- K3: squash + psi_mA conv2d (stride 8 in H, k=(8,3)) -------
// h3 = h2 / (1 + sq); h5[n,o,i,l] = bias[o] + sum_{kh,kw} h3[8i+kh, l+kw-1] w5[o,kh,kw]
__global__ __launch_bounds__(256) void k3_h5(const float* __restrict__ w5,
                                             const float* __restrict__ b5) {
    __shared__ float h3s[64 * 132];
    __shared__ float ws[64 * 24];
    __shared__ float bs[64];
    __shared__ float invs[64];
    int n  = blockIdx.y;
    int l0 = blockIdx.x * 128;

    if (threadIdx.x < 64) {
        invs[threadIdx.x] = 1.f / (1.f + g_sq[n * 64 + threadIdx.x]);
        bs[threadIdx.x]   = b5[threadIdx.x];
    }
    for (int i = threadIdx.x; i < 64 * 24; i += 256) ws[i] = w5[i];
    __syncthreads();
    for (int i = threadIdx.x; i < 64 * 130; i += 256) {
        int c = i / 130; int p = i - c * 130;
        int g = l0 - 1 + p;
        h3s[c * 132 + p] = (g >= 0 && g < LL) ? g_h2[(n * 64 + c) * LL + g] * invs[c]
                                              : 0.f;
    }
    __syncthreads();

    int warp = threadIdx.x >> 5, lane = threadIdx.x & 31;
    int lbase = lane * 4;                   // warp covers the full 128-wide tile
    int gl = l0 + lbase;

    #pragma unroll 1
    for (int i = 0; i < 8; i++) {
        float hv[8][6];
        #pragma unroll
        for (int kh = 0; kh < 8; kh++) {
            const float* r = h3s + (8 * i + kh) * 132 + lbase;   // 16B aligned
            float4 a = *(const float4*)r;
            float2 b = *(const float2*)(r + 4);
            hv[kh][0] = a.x; hv[kh][1] = a.y; hv[kh][2] = a.z;
            hv[kh][3] = a.w; hv[kh][4] = b.x; hv[kh][5] = b.y;
        }
        #pragma unroll 1
        for (int og = 0; og < 8; og++) {
            int o = og * 8 + warp;
            float bias = bs[o];
            float acc[4] = {bias, bias, bias, bias};
            #pragma unroll
            for (int kh = 0; kh < 8; kh++) {
                float w0 = ws[o * 24 + kh * 3 + 0];
                float w1 = ws[o * 24 + kh * 3 + 1];
                float w2 = ws[o * 24 + kh * 3 + 2];
                #pragma unroll
                for (int d = 0; d < 4; d++) {
                    acc[d] = fmaf(w0, hv[kh][d],     acc[d]);
                    acc[d] = fmaf(w1, hv[kh][d + 1], acc[d]);
                    acc[d] = fmaf(w2, hv[kh][d + 2], acc[d]);
                }
            }
            if (gl < LL) {
                float4 st = {acc[0], acc[1], acc[2], acc[3]};
                *(float4*)&g_h5[((n * 64 + o) * 8 + i) * LL + gl] = st;
            }
        }
    }
}

// ---------------- K4: 8x8 Gram per (n,o) + full routing -> coefficients -----
__global__ __launch_bounds__(256) void k4_routing() {
    int no = blockIdx.x;                       // 0..4095
    const float* H = g_h5 + (size_t)no * 8 * LL;

    float g[36];
    #pragma unroll
    for (int p = 0; p < 36; p++) g[p] = 0.f;

    for (int l = threadIdx.x; l < LL; l += 256) {
        float v[8];
        #pragma unroll
        for (int i = 0; i < 8; i++) v[i] = H[i * LL + l];
        int p = 0;
        #pragma unroll
        for (int i = 0; i < 8; i++)
            #pragma unroll
            for (int j = i; j < 8; j++) { g[p] = fmaf(v[i], v[j], g[p]); p++; }
    }

    __shared__ float red[8][36];
    int warp = threadIdx.x >> 5, lane = threadIdx.x & 31;
    #pragma unroll
    for (int p = 0; p < 36; p++) {
        float v = g[p];
        v += __shfl_down_sync(0xffffffffu, v, 16);
        v += __shfl_down_sync(0xffffffffu, v, 8);
        v += __shfl_down_sync(0xffffffffu, v, 4);
        v += __shfl_down_sync(0xffffffffu, v, 2);
        v += __shfl_down_sync(0xffffffffu, v, 1);
        if (lane == 0) red[warp][p] = v;
    }
    __syncthreads();

    if (threadIdx.x == 0) {
        float G[8][8];
        int p = 0;
        for (int i = 0; i < 8; i++)
            for (int j = i; j < 8; j++) {
                float s = 0.f;
                for (int w = 0; w < 8; w++) s += red[w][p];
                G[i][j] = s; G[j][i] = s; p++;
            }
        // iter 1: c = 1/8 uniformly
        float rowsum[8], tot = 0.f;
        for (int i = 0; i < 8; i++) {
            float s = 0.f;
            for (int j = 0; j < 8; j++) s += G[i][j];
            rowsum[i] = s; tot += s;
        }
        float sqn1 = tot * (1.f / 64.f);
        float inv1 = 1.f / (sqn1 + 1.f);
        float b[8], m = -1e30f;
        for (int i = 0; i < 8; i++) {
            b[i] = rowsum[i] * 0.125f * inv1;
            if (b[i] > m) m = b[i];
        }
        // iter 2: c = softmax(b); sqn2 = c^T G c; coef = c/(sqn2+1)
        float e[8], se = 0.f;
        for (int i = 0; i < 8; i++) { e[i] = expf(b[i] - m); se += e[i]; }
        float ise = 1.f / se;
        float c[8];
        for (int i = 0; i < 8; i++) c[i] = e[i] * ise;
        float sqn2 = 0.f;
        for (int i = 0; i < 8; i++)
            for (int j = 0; j < 8; j++) sqn2 += c[i] * c[j] * G[i][j];
        float k = 1.f / (sqn2 + 1.f);
        for (int i = 0; i < 8; i++) g_coef[no * 8 + i] = c[i] * k;
    }
}

// ---------------- K5: out[n,o,l] = sum_i coef_i * h5[n,o,i,l] ---------------
__global__ __launch_bounds__(256) void k5_out(float* __restrict__ out) {
    int no  = blockIdx.y;
    int idx = blockIdx.x * 256 + threadIdx.x;
    if (idx >= LL / 4) return;                 // LL % 4 == 0 -> 1125 float4s
    int l = idx * 4;
    const float* H = g_h5 + (size_t)no * 8 * LL;
    const float* C = g_coef + no * 8;
    float4 a = {0.f, 0.f, 0.f, 0.f};
    #pragma unroll
    for (int i = 0; i < 8; i++) {
        float c  = C[i];
        float4 h = *(const float4*)&H[i * LL + l];
        a.x = fmaf(c, h.x, a.x); a.y = fmaf(c, h.y, a.y);
        a.z = fmaf(c, h.z, a.z); a.w = fmaf(c, h.w, a.w);
    }
    *(float4*)&out[(size_t)no * LL + l] = a;
}

// ---------------- launch -----------------------------------------------------
extern "C" void kernel_launch(void* const* d_in, const int* in_sizes, int n_in,
                              void* d_out, int out_size) {
    // Identify inputs by element count (all distinct): robust to ordering.
    const float *x = nullptr, *w1 = nullptr, *w2 = nullptr, *w5 = nullptr, *b5 = nullptr;
    for (int i = 0; i < n_in; i++) {
        switch (in_sizes[i]) {
            case 288000: x  = (const float*)d_in[i]; break;  // (64,1,4500)
            case 448:    w1 = (const float*)d_in[i]; break;  // (64,1,7)
            case 20480:  w2 = (const float*)d_in[i]; break;  // (64,64,5)
            case 1536:   w5 = (const float*)d_in[i]; break;  // (64,1,8,3)
            case 64:     b5 = (const float*)d_in[i]; break;  // (64,)
        }
    }
    float* out = (float*)d_out;

    const size_t smem2 = SMEM2_FLOATS * sizeof(float);       // 115,968 B
    cudaFuncSetAttribute(k2_conv2, cudaFuncAttributeMaxDynamicSharedMemorySize,
                         (int)smem2);

    k0_zero_sq<<<16, 256>>>();
    k1_conv1 <<<dim3(9, NB), 256>>>(x, w1);
    k2_conv2 <<<dim3(36, NB), 256, smem2>>>(w2);
    k3_h5    <<<dim3(36, NB), 256>>>(w5, b5);
    k4_routing<<<NB * NOUT, 256>>>();
    k5_out   <<<dim3(5, NB * NOUT), 256>>>(out);
}

// round 7
// speedup vs baseline: 1.0744x; 1.0744x over previous
#include <cuda_runtime.h>

#define NB   64
#define LL   4500
#define KCH  64

typedef unsigned long long u64;

__device__ __forceinline__ u64 pk(float lo, float hi) {
    u64 r; asm("mov.b64 %0, {%1,%2};" : "=l"(r) : "f"(lo), "f"(hi)); return r;
}
__device__ __forceinline__ u64 pk1(float v) { return pk(v, v); }
__device__ __forceinline__ void upk(u64 p, float& lo, float& hi) {
    asm("mov.b64 {%0,%1}, %2;" : "=f"(lo), "=f"(hi) : "l"(p));
}
__device__ __forceinline__ u64 f2(u64 a, u64 b, u64 c) {
    u64 d; asm("fma.rn.f32x2 %0, %1, %2, %3;" : "=l"(d) : "l"(a), "l"(b), "l"(c));
    return d;
}

// ---------------- scratch ----------------------------------------------------
__device__ float g_h2[NB * KCH * LL];     // conv2 output (73.7 MB)
__device__ float g_sq[NB * KCH];          // sum_l h2^2
__device__ float g_gram[NB * 64 * 36];    // 8x8 Gram (upper tri) per (n,o)
__device__ float g_weff[NB * 64 * 3 * 64];// effective weights [n][c][kw][o]
__device__ float g_outb[NB * 64];         // effective bias per (n,o)

// ---------------- K0: zero accumulators --------------------------------------
__global__ void k0_zero() {
    int i = blockIdx.x * blockDim.x + threadIdx.x;
    if (i < NB * KCH) g_sq[i] = 0.f;
    if (i < NB * 64 * 36) g_gram[i] = 0.f;
}

// ---------------- K2: fused conv1(k=7) + conv2(k=5) + sum-of-squares ---------
// block 512 = 16 kgroups x 32 lgroups; tile 256 L; thread: 4k x 8l (FFMA2 over k)
#define K2_SMEM_FLOATS (64*264 + 20480 + 272 + 448 + 64)
__global__ __launch_bounds__(512) void k2_fused(const float* __restrict__ x,
                                                const float* __restrict__ w1,
                                                const float* __restrict__ w2) {
    extern __shared__ float sm[];
    float* h1s = sm;                   // [64][264], cols 0..259 used (halo 2)
    float* w2s = h1s + 64 * 264;       // [c][dk][k]  (20480)
    float* xs  = w2s + 20480;          // 266 used
    float* w1s = xs + 272;             // 448
    float* sqs = w1s + 448;            // 64
    int n  = blockIdx.y;
    int l0 = blockIdx.x * 256;
    int tid = threadIdx.x;

    for (int i = tid; i < 448; i += 512) w1s[i] = w1[i];
    for (int i = tid; i < 266; i += 512) {
        int g = l0 - 5 + i;
        xs[i] = (g >= 0 && g < LL) ? x[n * LL + g] : 0.f;
    }
    for (int i = tid; i < 20480; i += 512) {
        int k = i / 320; int r = i - k * 320; int c = r / 5; int dk = r - c * 5;
        w2s[c * 320 + dk * 64 + k] = w2[i];
    }
    if (tid < 64) sqs[tid] = 0.f;
    __syncthreads();

    // conv1 into smem (h1 tile with halo 2)
    for (int i = tid; i < 64 * 260; i += 512) {
        int c = i / 260; int p = i - c * 260;
        int g = l0 - 2 + p;
        float a = 0.f;
        if (g >= 0 && g < LL) {
            #pragma unroll
            for (int d = 0; d < 7; d++) a = fmaf(xs[p + d], w1s[c * 7 + d], a);
        }
        h1s[c * 264 + p] = a;
    }
    __syncthreads();

    int kg = tid >> 5, lg = tid & 31;
    int k0 = kg * 4, ll0 = lg * 8;

    u64 acc[2][8];
    #pragma unroll
    for (int a = 0; a < 2; a++)
        #pragma unroll
        for (int b = 0; b < 8; b++) acc[a][b] = 0ull;

    for (int c = 0; c < 64; c++) {
        const float* hr = h1s + c * 264 + ll0;
        float4 A = *(const float4*)hr;
        float4 B = *(const float4*)(hr + 4);
        float4 C = *(const float4*)(hr + 8);
        float hv[12] = {A.x, A.y, A.z, A.w, B.x, B.y, B.z, B.w, C.x, C.y, C.z, C.w};
        u64 hp[12];
        #pragma unroll
        for (int t = 0; t < 12; t++) hp[t] = pk1(hv[t]);
        const u64* wr = (const u64*)(w2s + c * 320 + k0);
        #pragma unroll
        for (int dk = 0; dk < 5; dk++) {
            u64 w0 = wr[dk * 32], w1p = wr[dk * 32 + 1];
            #pragma unroll
            for (int ll = 0; ll < 8; ll++) {
                acc[0][ll] = f2(w0,  hp[ll + dk], acc[0][ll]);
                acc[1][ll] = f2(w1p, hp[ll + dk], acc[1][ll]);
            }
        }
    }

    float r[4][8];
    #pragma unroll
    for (int ll = 0; ll < 8; ll++) {
        upk(acc[0][ll], r[0][ll], r[1][ll]);
        upk(acc[1][ll], r[2][ll], r[3][ll]);
    }
    float sl[4] = {0.f, 0.f, 0.f, 0.f};
    #pragma unroll
    for (int kk = 0; kk < 4; kk++) {
        size_t row = ((size_t)n * 64 + k0 + kk) * LL;
        #pragma unroll
        for (int v = 0; v < 2; v++) {
            int gl = l0 + ll0 + v * 4;
            if (gl < LL) {
                float4 st = {r[kk][v*4+0], r[kk][v*4+1], r[kk][v*4+2], r[kk][v*4+3]};
                *(float4*)&g_h2[row + gl] = st;
                sl[kk] += st.x*st.x + st.y*st.y + st.z*st.z + st.w*st.w;
            }
        }
    }
    #pragma unroll
    for (int kk = 0; kk < 4; kk++) atomicAdd(&sqs[k0 + kk], sl[kk]);
    __syncthreads();
    if (tid < 64) atomicAdd(&g_sq[n * 64 + tid], sqs[tid]);
}

// ---------------- K3: fused squash + psi_mA conv + 8x8 Gram ------------------
// h5 is computed in registers (never written); Gram partials go to g_gram.
// block 256 = 64 o x 4 lc; tile 128 L; thread handles 4 L per step (2 pairs).
__global__ __launch_bounds__(256) void k_gram(const float* __restrict__ w5,
                                              const float* __restrict__ b5) {
    __shared__ float h3s[64 * 132];       // cols 0..129 (halo 1), global l0-1+p
    __shared__ u64   ws2[64 * 24];        // (w,w) duplicated pairs
    __shared__ u64   bp[64];
    __shared__ float invs[64];
    int n  = blockIdx.y;
    int l0 = blockIdx.x * 128;
    int tid = threadIdx.x;

    if (tid < 64) {
        invs[tid] = 1.f / (1.f + g_sq[n * 64 + tid]);
        bp[tid]   = pk1(b5[tid]);
    }
    for (int i = tid; i < 64 * 24; i += 256) ws2[i] = pk1(w5[i]);
    __syncthreads();
    for (int i = tid; i < 64 * 130; i += 256) {
        int c = i / 130; int p = i - c * 130;
        int g = l0 - 1 + p;
        h3s[c * 132 + p] = (g >= 0 && g < LL) ? g_h2[((size_t)n*64+c)*LL + g] * invs[c]
                                              : 0.f;
    }
    __syncthreads();

    int o = tid >> 2, lc = tid & 3;
    const u64* wo = ws2 + o * 24;
    u64 bias = bp[o];

    u64 gr[36];
    #pragma unroll
    for (int p = 0; p < 36; p++) gr[p] = 0ull;

    for (int s = 0; s < 8; s++) {
        int q  = lc + 4 * s;          // quad 0..31
        int cb = 4 * q;               // col base
        u64 vA[8], vB[8];
        #pragma unroll
        for (int i = 0; i < 8; i++) {
            u64 a = bias, b = bias;
            #pragma unroll
            for (int kh = 0; kh < 8; kh++) {
                const float* rp = h3s + (8*i + kh) * 132 + cb;
                u64 u01 = *(const u64*)rp;
                u64 u23 = *(const u64*)(rp + 2);
                u64 u45 = *(const u64*)(rp + 4);
                float d0, c1, c2, c3, c4, d5;
                upk(u01, d0, c1); upk(u23, c2, c3); upk(u45, c4, d5);
                u64 m12 = pk(c1, c2), m34 = pk(c3, c4);
                u64 w0 = wo[kh*3+0], w1 = wo[kh*3+1], w2v = wo[kh*3+2];
                a = f2(w0, u01, a); a = f2(w1, m12, a); a = f2(w2v, u23, a);
                b = f2(w0, u23, b); b = f2(w1, m34, b); b = f2(w2v, u45, b);
            }
            vA[i] = a; vB[i] = b;
        }
        // mask padded L positions (only last tile's tail)
        int base = l0 + 4 * q;
        if (base + 3 >= LL) {
            #pragma unroll
            for (int i = 0; i < 8; i++) {
                float a0, a1, b0, b1;
                upk(vA[i], a0, a1); upk(vB[i], b0, b1);
                if (base     >= LL) a0 = 0.f;
                if (base + 1 >= LL) a1 = 0.f;
                if (base + 2 >= LL) b0 = 0.f;
                if (base + 3 >= LL) b1 = 0.f;
                vA[i] = pk(a0, a1); vB[i] = pk(b0, b1);
            }
        }
        int p = 0;
        #pragma unroll
        for (int i = 0; i < 8; i++)
            #pragma unroll
            for (int j = i; j < 8; j++) {
                gr[p] = f2(vA[i], vA[j], gr[p]);
                gr[p] = f2(vB[i], vB[j], gr[p]);
                p++;
            }
    }

    int no = n * 64 + o;
    #pragma unroll
    for (int p = 0; p < 36; p++) {
        float lo, hi; upk(gr[p], lo, hi);
        float v = lo + hi;
        v += __shfl_down_sync(0xffffffffu, v, 2, 4);
        v += __shfl_down_sync(0xffffffffu, v, 1, 4);
        if (lc == 0) atomicAdd(&g_gram[no * 36 + p], v);
    }
}

// ---------------- K4: routing from Gram -> effective weights -----------------
__global__ void k_route(const float* __restrict__ w5, const float* __restrict__ b5) {
    int t = blockIdx.x * 256 + threadIdx.x;
    if (t >= NB * 64) return;
    int n = t >> 6, o = t & 63;

    float G[8][8];
    {
        const float* gp = g_gram + t * 36;
        int p = 0;
        for (int i = 0; i < 8; i++)
            for (int j = i; j < 8; j++) { float v = gp[p++]; G[i][j] = v; G[j][i] = v; }
    }
    // iter 1: c = 1/8
    float rowsum[8], tot = 0.f;
    for (int i = 0; i < 8; i++) {
        float s = 0.f;
        for (int j = 0; j < 8; j++) s += G[i][j];
        rowsum[i] = s; tot += s;
    }
    float sqn1 = tot * (1.f / 64.f);
    float inv1 = 1.f / (sqn1 + 1.f);
    float b[8], m = -1e30f;
    for (int i = 0; i < 8; i++) {
        b[i] = rowsum[i] * 0.125f * inv1;
        if (b[i] > m) m = b[i];
    }
    // iter 2
    float e[8], se = 0.f;
    for (int i = 0; i < 8; i++) { e[i] = expf(b[i] - m); se += e[i]; }
    float ise = 1.f / se;
    float c[8];
    for (int i = 0; i < 8; i++) c[i] = e[i] * ise;
    float sqn2 = 0.f;
    for (int i = 0; i < 8; i++)
        for (int j = 0; j < 8; j++) sqn2 += c[i] * c[j] * G[i][j];
    float k = 1.f / (sqn2 + 1.f);
    float coef[8], csum = 0.f;
    for (int i = 0; i < 8; i++) { coef[i] = c[i] * k; csum += coef[i]; }

    g_outb[t] = csum * b5[o];
    // weff[n][c=8i+kh][kw][o] = coef_i * w5[o][kh][kw]   (o-contig -> coalesced)
    for (int i = 0; i < 8; i++)
        for (int kh = 0; kh < 8; kh++) {
            float cf = coef[i];
            int cc = 8 * i + kh;
            #pragma unroll
            for (int kw = 0; kw < 3; kw++)
                g_weff[(((n * 64 + cc) * 3 + kw) * 64) + o] = cf * w5[o*24 + kh*3 + kw];
        }
}

// ---------------- K5: output conv (64ch -> 64o, k=3, per-n weights) ----------
// out[n,o,l] = outb[n,o] + sum_{c,kw} h3[c][l+kw-1] * weff[n][c][kw][o]
#define K5_SMEM_FLOATS (64*264 + 12288 + 64 + 64)
__global__ __launch_bounds__(512) void k5_out(float* __restrict__ out) {
    extern __shared__ float sm[];
    float* h3s  = sm;                   // [64][264], cols 0..259 used (halo 1+tail)
    float* wsb  = h3s + 64 * 264;       // [c][kw][o] 12288
    float* obs  = wsb + 12288;          // 64
    float* invs = obs + 64;             // 64
    int n  = blockIdx.y;
    int l0 = blockIdx.x * 256;
    int tid = threadIdx.x;

    if (tid < 64) {
        invs[tid] = 1.f / (1.f + g_sq[n * 64 + tid]);
        obs[tid]  = g_outb[n * 64 + tid];
    }
    for (int i = tid; i < 12288; i += 512) wsb[i] = g_weff[n * 12288 + i];
    __syncthreads();
    for (int i = tid; i < 64 * 260; i += 512) {
        int c = i / 260; int p = i - c * 260;
        int g = l0 - 1 + p;
        h3s[c * 264 + p] = (g >= 0 && g < LL) ? g_h2[((size_t)n*64+c)*LL + g] * invs[c]
                                              : 0.f;
    }
    __syncthreads();

    int og = tid >> 5, lg = tid & 31;
    int o0 = og * 4, ll0 = lg * 8;

    u64 ob0 = *(const u64*)(obs + o0);
    u64 ob1 = *(const u64*)(obs + o0 + 2);
    u64 acc[2][8];
    #pragma unroll
    for (int ll = 0; ll < 8; ll++) { acc[0][ll] = ob0; acc[1][ll] = ob1; }

    for (int c = 0; c < 64; c++) {
        const float* hr = h3s + c * 264 + ll0;
        float4 A = *(const float4*)hr;
        float4 B = *(const float4*)(hr + 4);
        float2 C = *(const float2*)(hr + 8);
        float hv[10] = {A.x, A.y, A.z, A.w, B.x, B.y, B.z, B.w, C.x, C.y};
        u64 hp[10];
        #pragma unroll
        for (int t = 0; t < 10; t++) hp[t] = pk1(hv[t]);
        const float* wb = wsb + c * 192;
        #pragma unroll
        for (int kw = 0; kw < 3; kw++) {
            u64 w0 = *(const u64*)(wb + kw * 64 + o0);
            u64 w1 = *(const u64*)(wb + kw * 64 + o0 + 2);
            #pragma unroll
            for (int ll = 0; ll < 8; ll++) {
                acc[0][ll] = f2(w0, hp[ll + kw], acc[0][ll]);
                acc[1][ll] = f2(w1, hp[ll + kw], acc[1][ll]);
            }
        }
    }

    float r[4][8];
    #pragma unroll
    for (int ll = 0; ll < 8; ll++) {
        upk(acc[0][ll], r[0][ll], r[1][ll]);
        upk(acc[1][ll], r[2][ll], r[3][ll]);
    }
    #pragma unroll
    for (int oo = 0; oo < 4; oo++) {
        size_t row = ((size_t)n * 64 + o0 + oo) * LL;
        #pragma unroll
        for (int v = 0; v < 2; v++) {
            int gl = l0 + ll0 + v * 4;
            if (gl < LL) {
                float4 st = {r[oo][v*4+0], r[oo][v*4+1], r[oo][v*4+2], r[oo][v*4+3]};
                *(float4*)&out[row + gl] = st;
            }
        }
    }
}

// ---------------- launch -----------------------------------------------------
extern "C" void kernel_launch(void* const* d_in, const int* in_sizes, int n_in,
                              void* d_out, int out_size) {
    const float *x = nullptr, *w1 = nullptr, *w2 = nullptr, *w5 = nullptr, *b5 = nullptr;
    for (int i = 0; i < n_in; i++) {
        switch (in_sizes[i]) {
            case 288000: x  = (const float*)d_in[i]; break;
            case 448:    w1 = (const float*)d_in[i]; break;
            case 20480:  w2 = (const float*)d_in[i]; break;
            case 1536:   w5 = (const float*)d_in[i]; break;
            case 64:     b5 = (const float*)d_in[i]; break;
        }
    }
    float* out = (float*)d_out;

    static int attr_done = 0;
    const size_t smem2 = K2_SMEM_FLOATS * sizeof(float);   // 152,640 B
    const size_t smem5 = K5_SMEM_FLOATS * sizeof(float);   // 117,248 B
    cudaFuncSetAttribute(k2_fused, cudaFuncAttributeMaxDynamicSharedMemorySize, (int)smem2);
    cudaFuncSetAttribute(k5_out,   cudaFuncAttributeMaxDynamicSharedMemorySize, (int)smem5);
    (void)attr_done;

    k0_zero  <<<(NB*64*36 + 255)/256, 256>>>();
    k2_fused <<<dim3(18, NB), 512, smem2>>>(x, w1, w2);
    k_gram   <<<dim3(36, NB), 256>>>(w5, b5);
    k_route  <<<16, 256>>>(w5, b5);
    k5_out   <<<dim3(18, NB), 512, smem5>>>(out);
}

// round 8
// speedup vs baseline: 1.0764x; 1.0019x over previous
#include <cuda_runtime.h>

#define NB   64
#define LL   4500
#define KCH  64

typedef unsigned long long u64;

__device__ __forceinline__ u64 pk(float lo, float hi) {
    u64 r; asm("mov.b64 %0, {%1,%2};" : "=l"(r) : "f"(lo), "f"(hi)); return r;
}
__device__ __forceinline__ u64 pk1(float v) { return pk(v, v); }
__device__ __forceinline__ void upk(u64 p, float& lo, float& hi) {
    asm("mov.b64 {%0,%1}, %2;" : "=f"(lo), "=f"(hi) : "l"(p));
}
__device__ __forceinline__ u64 f2(u64 a, u64 b, u64 c) {
    u64 d; asm("fma.rn.f32x2 %0, %1, %2, %3;" : "=l"(d) : "l"(a), "l"(b), "l"(c));
    return d;
}

// ---------------- scratch ----------------------------------------------------
__device__ float g_h2[NB * KCH * LL];     // conv2 output (73.7 MB)
__device__ float g_sq[NB * KCH];          // sum_l h2^2
__device__ float g_gram[NB * 64 * 36];    // 8x8 Gram (upper tri) per (n,o)
__device__ float g_weff[NB * 64 * 3 * 64];// effective weights [n][c][kw][o]
__device__ float g_outb[NB * 64];         // effective bias per (n,o)

// ---------------- K0: zero accumulators --------------------------------------
__global__ void k0_zero() {
    int i = blockIdx.x * blockDim.x + threadIdx.x;
    if (i < NB * KCH) g_sq[i] = 0.f;
    if (i < NB * 64 * 36) g_gram[i] = 0.f;
}

// ---------------- K2: fused conv1(k=7) + conv2(k=5) + sum-of-squares ---------
// block 512 = 16 kgroups x 32 lgroups; tile 256 L; thread: 4k x 8l (FFMA2 over k)
#define K2_SMEM_FLOATS (64*264 + 20480 + 272 + 448 + 64)
__global__ __launch_bounds__(512) void k2_fused(const float* __restrict__ x,
                                                const float* __restrict__ w1,
                                                const float* __restrict__ w2) {
    extern __shared__ float sm[];
    float* h1s = sm;                   // [64][264], cols 0..259 used (halo 2)
    float* w2s = h1s + 64 * 264;       // [c][dk][k]  (20480)
    float* xs  = w2s + 20480;          // 266 used
    float* w1s = xs + 272;             // 448
    float* sqs = w1s + 448;            // 64
    int n  = blockIdx.y;
    int l0 = blockIdx.x * 256;
    int tid = threadIdx.x;

    for (int i = tid; i < 448; i += 512) w1s[i] = w1[i];
    for (int i = tid; i < 266; i += 512) {
        int g = l0 - 5 + i;
        xs[i] = (g >= 0 && g < LL) ? x[n * LL + g] : 0.f;
    }
    for (int i = tid; i < 20480; i += 512) {
        int k = i / 320; int r = i - k * 320; int c = r / 5; int dk = r - c * 5;
        w2s[c * 320 + dk * 64 + k] = w2[i];
    }
    if (tid < 64) sqs[tid] = 0.f;
    __syncthreads();

    // conv1 into smem (h1 tile with halo 2)
    for (int i = tid; i < 64 * 260; i += 512) {
        int c = i / 260; int p = i - c * 260;
        int g = l0 - 2 + p;
        float a = 0.f;
        if (g >= 0 && g < LL) {
            #pragma unroll
            for (int d = 0; d < 7; d++) a = fmaf(xs[p + d], w1s[c * 7 + d], a);
        }
        h1s[c * 264 + p] = a;
    }
    __syncthreads();

    int kg = tid >> 5, lg = tid & 31;
    int k0 = kg * 4, ll0 = lg * 8;

    u64 acc[2][8];
    #pragma unroll
    for (int a = 0; a < 2; a++)
        #pragma unroll
        for (int b = 0; b < 8; b++) acc[a][b] = 0ull;

    for (int c = 0; c < 64; c++) {
        const float* hr = h1s + c * 264 + ll0;
        float4 A = *(const float4*)hr;
        float4 B = *(const float4*)(hr + 4);
        float4 C = *(const float4*)(hr + 8);
        float hv[12] = {A.x, A.y, A.z, A.w, B.x, B.y, B.z, B.w, C.x, C.y, C.z, C.w};
        u64 hp[12];
        #pragma unroll
        for (int t = 0; t < 12; t++) hp[t] = pk1(hv[t]);
        const u64* wr = (const u64*)(w2s + c * 320 + k0);
        #pragma unroll
        for (int dk = 0; dk < 5; dk++) {
            u64 w0 = wr[dk * 32], w1p = wr[dk * 32 + 1];
            #pragma unroll
            for (int ll = 0; ll < 8; ll++) {
                acc[0][ll] = f2(w0,  hp[ll + dk], acc[0][ll]);
                acc[1][ll] = f2(w1p, hp[ll + dk], acc[1][ll]);
            }
        }
    }

    float r[4][8];
    #pragma unroll
    for (int ll = 0; ll < 8; ll++) {
        upk(acc[0][ll], r[0][ll], r[1][ll]);
        upk(acc[1][ll], r[2][ll], r[3][ll]);
    }
    float sl[4] = {0.f, 0.f, 0.f, 0.f};
    #pragma unroll
    for (int kk = 0; kk < 4; kk++) {
        size_t row = ((size_t)n * 64 + k0 + kk) * LL;
        #pragma unroll
        for (int v = 0; v < 2; v++) {
            int gl = l0 + ll0 + v * 4;
            if (gl < LL) {
                float4 st = {r[kk][v*4+0], r[kk][v*4+1], r[kk][v*4+2], r[kk][v*4+3]};
                *(float4*)&g_h2[row + gl] = st;
                sl[kk] += st.x*st.x + st.y*st.y + st.z*st.z + st.w*st.w;
            }
        }
    }
    #pragma unroll
    for (int kk = 0; kk < 4; kk++) atomicAdd(&sqs[k0 + kk], sl[kk]);
    __syncthreads();
    if (tid < 64) atomicAdd(&g_sq[n * 64 + tid], sqs[tid]);
}

// ---------------- K3: fused squash + psi_mA conv + 8x8 Gram ------------------
// h5 is computed in registers (never written); Gram partials go to g_gram.
// block 256 = 64 o x 4 lc; tile 128 L; thread handles 4 L per step (2 pairs).
__global__ __launch_bounds__(256) void k_gram(const float* __restrict__ w5,
                                              const float* __restrict__ b5) {
    __shared__ float h3s[64 * 132];       // cols 0..129 (halo 1), global l0-1+p
    __shared__ u64   ws2[64 * 24];        // (w,w) duplicated pairs
    __shared__ u64   bp[64];
    __shared__ float invs[64];
    int n  = blockIdx.y;
    int l0 = blockIdx.x * 128;
    int tid = threadIdx.x;

    if (tid < 64) {
        invs[tid] = 1.f / (1.f + g_sq[n * 64 + tid]);
        bp[tid]   = pk1(b5[tid]);
    }
    for (int i = tid; i < 64 * 24; i += 256) ws2[i] = pk1(w5[i]);
    __syncthreads();
    for (int i = tid; i < 64 * 130; i += 256) {
        int c = i / 130; int p = i - c * 130;
        int g = l0 - 1 + p;
        h3s[c * 132 + p] = (g >= 0 && g < LL) ? g_h2[((size_t)n*64+c)*LL + g] * invs[c]
                                              : 0.f;
    }
    __syncthreads();

    int o = tid >> 2, lc = tid & 3;
    const u64* wo = ws2 + o * 24;
    u64 bias = bp[o];

    u64 gr[36];
    #pragma unroll
    for (int p = 0; p < 36; p++) gr[p] = 0ull;

    for (int s = 0; s < 8; s++) {
        int q  = lc + 4 * s;          // quad 0..31
        int cb = 4 * q;               // col base
        u64 vA[8], vB[8];
        #pragma unroll
        for (int i = 0; i < 8; i++) {
            u64 a = bias, b = bias;
            #pragma unroll
            for (int kh = 0; kh < 8; kh++) {
                const float* rp = h3s + (8*i + kh) * 132 + cb;
                u64 u01 = *(const u64*)rp;
                u64 u23 = *(const u64*)(rp + 2);
                u64 u45 = *(const u64*)(rp + 4);
                float d0, c1, c2, c3, c4, d5;
                upk(u01, d0, c1); upk(u23, c2, c3); upk(u45, c4, d5);
                u64 m12 = pk(c1, c2), m34 = pk(c3, c4);
                u64 w0 = wo[kh*3+0], w1 = wo[kh*3+1], w2v = wo[kh*3+2];
                a = f2(w0, u01, a); a = f2(w1, m12, a); a = f2(w2v, u23, a);
                b = f2(w0, u23, b); b = f2(w1, m34, b); b = f2(w2v, u45, b);
            }
            vA[i] = a; vB[i] = b;
        }
        // mask padded L positions (only last tile's tail)
        int base = l0 + 4 * q;
        if (base + 3 >= LL) {
            #pragma unroll
            for (int i = 0; i < 8; i++) {
                float a0, a1, b0, b1;
                upk(vA[i], a0, a1); upk(vB[i], b0, b1);
                if (base     >= LL) a0 = 0.f;
                if (base + 1 >= LL) a1 = 0.f;
                if (base + 2 >= LL) b0 = 0.f;
                if (base + 3 >= LL) b1 = 0.f;
                vA[i] = pk(a0, a1); vB[i] = pk(b0, b1);
            }
        }
        int p = 0;
        #pragma unroll
        for (int i = 0; i < 8; i++)
            #pragma unroll
            for (int j = i; j < 8; j++) {
                gr[p] = f2(vA[i], vA[j], gr[p]);
                gr[p] = f2(vB[i], vB[j], gr[p]);
                p++;
            }
    }

    int no = n * 64 + o;
    #pragma unroll
    for (int p = 0; p < 36; p++) {
        float lo, hi; upk(gr[p], lo, hi);
        float v = lo + hi;
        v += __shfl_down_sync(0xffffffffu, v, 2, 4);
        v += __shfl_down_sync(0xffffffffu, v, 1, 4);
        if (lc == 0) atomicAdd(&g_gram[no * 36 + p], v);
    }
}

// ---------------- K4: routing from Gram -> effective weights -----------------
__global__ void k_route(const float* __restrict__ w5, const float* __restrict__ b5) {
    int t = blockIdx.x * 256 + threadIdx.x;
    if (t >= NB * 64) return;
    int n = t >> 6, o = t & 63;

    float G[8][8];
    {
        const float* gp = g_gram + t * 36;
        int p = 0;
        for (int i = 0; i < 8; i++)
            for (int j = i; j < 8; j++) { float v = gp[p++]; G[i][j] = v; G[j][i] = v; }
    }
    // iter 1: c = 1/8
    float rowsum[8], tot = 0.f;
    for (int i = 0; i < 8; i++) {
        float s = 0.f;
        for (int j = 0; j < 8; j++) s += G[i][j];
        rowsum[i] = s; tot += s;
    }
    float sqn1 = tot * (1.f / 64.f);
    float inv1 = 1.f / (sqn1 + 1.f);
    float b[8], m = -1e30f;
    for (int i = 0; i < 8; i++) {
        b[i] = rowsum[i] * 0.125f * inv1;
        if (b[i] > m) m = b[i];
    }
    // iter 2
    float e[8], se = 0.f;
    for (int i = 0; i < 8; i++) { e[i] = expf(b[i] - m); se += e[i]; }
    float ise = 1.f / se;
    float c[8];
    for (int i = 0; i < 8; i++) c[i] = e[i] * ise;
    float sqn2 = 0.f;
    for (int i = 0; i < 8; i++)
        for (int j = 0; j < 8; j++) sqn2 += c[i] * c[j] * G[i][j];
    float k = 1.f / (sqn2 + 1.f);
    float coef[8], csum = 0.f;
    for (int i = 0; i < 8; i++) { coef[i] = c[i] * k; csum += coef[i]; }

    g_outb[t] = csum * b5[o];
    // weff[n][c=8i+kh][kw][o] = coef_i * w5[o][kh][kw]   (o-contig -> coalesced)
    for (int i = 0; i < 8; i++)
        for (int kh = 0; kh < 8; kh++) {
            float cf = coef[i];
            int cc = 8 * i + kh;
            #pragma unroll
            for (int kw = 0; kw < 3; kw++)
                g_weff[(((n * 64 + cc) * 3 + kw) * 64) + o] = cf * w5[o*24 + kh*3 + kw];
        }
}

// ---------------- K5: output conv (64ch -> 64o, k=3, per-n weights) ----------
// out[n,o,l] = outb[n,o] + sum_{c,kw} h3[c][l+kw-1] * weff[n][c][kw][o]
#define K5_SMEM_FLOATS (64*264 + 12288 + 64 + 64)
__global__ __launch_bounds__(512) void k5_out(float* __restrict__ out) {
    extern __shared__ float sm[];
    float* h3s  = sm;                   // [64][264], cols 0..259 used (halo 1+tail)
    float* wsb  = h3s + 64 * 264;       // [c][kw][o] 12288
    float* obs  = wsb + 12288;          // 64
    float* invs = obs + 64;             // 64
    int n  = blockIdx.y;
    int l0 = blockIdx.x * 256;
    int tid = threadIdx.x;

    if (tid < 64) {
        invs[tid] = 1.f / (1.f + g_sq[n * 64 + tid]);
        obs[tid]  = g_outb[n * 64 + tid];
    }
    for (int i = tid; i < 12288; i += 512) wsb[i] = g_weff[n * 12288 + i];
    __syncthreads();
    for (int i = tid; i < 64 * 260; i += 512) {
        int c = i / 260; int p = i - c * 260;
        int g = l0 - 1 + p;
        h3s[c * 264 + p] = (g >= 0 && g < LL) ? g_h2[((size_t)n*64+c)*LL + g] * invs[c]
                                              : 0.f;
    }
    __syncthreads();

    int og = tid >> 5, lg = tid & 31;
    int o0 = og * 4, ll0 = lg * 8;

    u64 ob0 = *(const u64*)(obs + o0);
    u64 ob1 = *(const u64*)(obs + o0 + 2);
    u64 acc[2][8];
    #pragma unroll
    for (int ll = 0; ll < 8; ll++) { acc[0][ll] = ob0; acc[1][ll] = ob1; }

    for (int c = 0; c < 64; c++) {
        const float* hr = h3s + c * 264 + ll0;
        float4 A = *(const float4*)hr;
        float4 B = *(const float4*)(hr + 4);
        float2 C = *(const float2*)(hr + 8);
        float hv[10] = {A.x, A.y, A.z, A.w, B.x, B.y, B.z, B.w, C.x, C.y};
        u64 hp[10];
        #pragma unroll
        for (int t = 0; t < 10; t++) hp[t] = pk1(hv[t]);
        const float* wb = wsb + c * 192;
        #pragma unroll
        for (int kw = 0; kw < 3; kw++) {
            u64 w0 = *(const u64*)(wb + kw * 64 + o0);
            u64 w1 = *(const u64*)(wb + kw * 64 + o0 + 2);
            #pragma unroll
            for (int ll = 0; ll < 8; ll++) {
                acc[0][ll] = f2(w0, hp[ll + kw], acc[0][ll]);
                acc[1][ll] = f2(w1, hp[ll + kw], acc[1][ll]);
            }
        }
    }

    float r[4][8];
    #pragma unroll
    for (int ll = 0; ll < 8; ll++) {
        upk(acc[0][ll], r[0][ll], r[1][ll]);
        upk(acc[1][ll], r[2][ll], r[3][ll]);
    }
    #pragma unroll
    for (int oo = 0; oo < 4; oo++) {
        size_t row = ((size_t)n * 64 + o0 + oo) * LL;
        #pragma unroll
        for (int v = 0; v < 2; v++) {
            int gl = l0 + ll0 + v * 4;
            if (gl < LL) {
                float4 st = {r[oo][v*4+0], r[oo][v*4+1], r[oo][v*4+2], r[oo][v*4+3]};
                *(float4*)&out[row + gl] = st;
            }
        }
    }
}

// ---------------- launch -----------------------------------------------------
extern "C" void kernel_launch(void* const* d_in, const int* in_sizes, int n_in,
                              void* d_out, int out_size) {
    const float *x = nullptr, *w1 = nullptr, *w2 = nullptr, *w5 = nullptr, *b5 = nullptr;
    for (int i = 0; i < n_in; i++) {
        switch (in_sizes[i]) {
            case 288000: x  = (const float*)d_in[i]; break;
            case 448:    w1 = (const float*)d_in[i]; break;
            case 20480:  w2 = (const float*)d_in[i]; break;
            case 1536:   w5 = (const float*)d_in[i]; break;
            case 64:     b5 = (const float*)d_in[i]; break;
        }
    }
    float* out = (float*)d_out;

    static int attr_done = 0;
    const size_t smem2 = K2_SMEM_FLOATS * sizeof(float);   // 152,640 B
    const size_t smem5 = K5_SMEM_FLOATS * sizeof(float);   // 117,248 B
    cudaFuncSetAttribute(k2_fused, cudaFuncAttributeMaxDynamicSharedMemorySize, (int)smem2);
    cudaFuncSetAttribute(k5_out,   cudaFuncAttributeMaxDynamicSharedMemorySize, (int)smem5);
    (void)attr_done;

    k0_zero  <<<(NB*64*36 + 255)/256, 256>>>();
    k2_fused <<<dim3(18, NB), 512, smem2>>>(x, w1, w2);
    k_gram   <<<dim3(36, NB), 256>>>(w5, b5);
    k_route  <<<16, 256>>>(w5, b5);
    k5_out   <<<dim3(18, NB), 512, smem5>>>(out);
}